// round 4
// baseline (speedup 1.0000x reference)
#include <cuda_runtime.h>
#include <cuda_bf16.h>
#include <cstdint>

// Problem constants
#define NB   8
#define NH   8
#define ND   32
#define NN   1024
#define CDIM 256
#define QKV_M 768
#define SCALE_F 0.17677669529663687f
#define L2E 1.4426950408889634f

// Scratch (device globals — no allocation allowed)
__device__ float g_xt[NB * CDIM * NN];    // tf32-rounded X
__device__ float g_wq[QKV_M * CDIM];      // tf32-rounded w_qkv
__device__ float g_wo[CDIM * CDIM];       // tf32-rounded w_out
__device__ float g_qt[NB * NH * NN * ND]; // scaled+rounded Q, [b][h][n][d]
__device__ float g_kt[NB * NH * NN * ND]; // rounded K
__device__ float g_vt[NB * NH * NN * ND]; // rounded V
__device__ float g_ao[NB * CDIM * NN];    // rounded attention out, [b][c][n]

// ---------------------------------------------------------------------------
// helpers
// ---------------------------------------------------------------------------
__device__ __forceinline__ uint32_t f2tf(float x) {
    uint32_t r;
    asm("cvt.rna.tf32.f32 %0, %1;" : "=r"(r) : "f"(x));
    return r;
}
__device__ __forceinline__ float f2tff(float x) { return __uint_as_float(f2tf(x)); }

__device__ __forceinline__ void mma_tf32(float c[4],
                                         uint32_t a0, uint32_t a1, uint32_t a2, uint32_t a3,
                                         uint32_t b0, uint32_t b1) {
    asm volatile(
        "mma.sync.aligned.m16n8k8.row.col.f32.tf32.tf32.f32 "
        "{%0,%1,%2,%3}, {%4,%5,%6,%7}, {%8,%9}, {%0,%1,%2,%3};\n"
        : "+f"(c[0]), "+f"(c[1]), "+f"(c[2]), "+f"(c[3])
        : "r"(a0), "r"(a1), "r"(a2), "r"(a3), "r"(b0), "r"(b1));
}

__device__ __forceinline__ float ex2f(float x) {
    float r;
    asm("ex2.approx.ftz.f32 %0, %1;" : "=f"(r) : "f"(x));
    return r;
}

__device__ __forceinline__ void cp16(uint32_t dst_smem, const void* src) {
    asm volatile("cp.async.cg.shared.global [%0], [%1], 16;\n" :: "r"(dst_smem), "l"(src));
}
__device__ __forceinline__ void cp_commit() { asm volatile("cp.async.commit_group;\n"); }
__device__ __forceinline__ void cp_wait1() { asm volatile("cp.async.wait_group 1;\n"); }
__device__ __forceinline__ void cp_wait0() { asm volatile("cp.async.wait_group 0;\n"); }

// ---------------------------------------------------------------------------
// Kernel 0: tf32-round X, w_qkv, w_out into scratch
// ---------------------------------------------------------------------------
#define NX4  (NB * CDIM * NN / 4)
#define NWQ4 (QKV_M * CDIM / 4)
#define NWO4 (CDIM * CDIM / 4)

__global__ __launch_bounds__(256) void cvt_kernel(const float* __restrict__ x,
                                                  const float* __restrict__ wq,
                                                  const float* __restrict__ wo)
{
    int idx = blockIdx.x * 256 + threadIdx.x;
    if (idx >= NX4 + NWQ4 + NWO4) return;
    const float4* src; float4* dst; int j;
    if (idx < NX4)             { src = (const float4*)x;  dst = (float4*)g_xt; j = idx; }
    else if (idx < NX4 + NWQ4) { src = (const float4*)wq; dst = (float4*)g_wq; j = idx - NX4; }
    else                       { src = (const float4*)wo; dst = (float4*)g_wo; j = idx - NX4 - NWQ4; }
    float4 v = src[j];
    v.x = f2tff(v.x); v.y = f2tff(v.y); v.z = f2tff(v.z); v.w = f2tff(v.w);
    dst[j] = v;
}

// ---------------------------------------------------------------------------
// tf32 MMA GEMM core: C(MxN)=A(MxK)*B(KxN), K=256, tile 128x128x16,
// cp.async 2-stage double buffer, STATIC smem (37KB). 256 threads = 8 warps
// (4m x 2n), warp tile 32x64.
// ---------------------------------------------------------------------------
#define GBM 128
#define GBN 128
#define GBK 16
#define APAD 20    // (g*20+tig) mod 32 distinct
#define BPAD 136   // (tig*8+g) distinct
#define A_STG (GBM * APAD)
#define B_STG (GBK * BPAD)

struct GemmAcc { float acc[2][8][4]; };

struct GemmSmem {
    uint32_t As[2][A_STG];
    uint32_t Bs[2][B_STG];
};

__device__ __forceinline__ void gemm_issue(GemmSmem* S, int s,
                                           const float* __restrict__ Ag,
                                           const float* __restrict__ Bg,
                                           int m0, int n0, int k0, int tid)
{
    uint32_t a_base = (uint32_t)__cvta_generic_to_shared(&S->As[s][0]);
    uint32_t b_base = (uint32_t)__cvta_generic_to_shared(&S->Bs[s][0]);
    // A tile 128x16 = 512 f4; map row=slot&127, f4=slot>>7 (conflict-free)
    #pragma unroll
    for (int i = 0; i < 2; i++) {
        int slot = i * 256 + tid;
        int row = slot & 127, f4 = slot >> 7;
        cp16(a_base + (uint32_t)(row * APAD + 4 * f4) * 4,
             Ag + (m0 + row) * CDIM + k0 + 4 * f4);
    }
    // B tile 16x128 = 512 f4
    #pragma unroll
    for (int i = 0; i < 2; i++) {
        int slot = i * 256 + tid;
        int row = slot >> 5, f4 = slot & 31;
        cp16(b_base + (uint32_t)(row * BPAD + 4 * f4) * 4,
             Bg + (k0 + row) * NN + n0 + 4 * f4);
    }
    cp_commit();
}

__device__ __forceinline__ void gemm_core(GemmSmem* S,
                                          const float* __restrict__ Ag,
                                          const float* __restrict__ Bg,
                                          int m0, int n0, GemmAcc& R)
{
    const int tid = threadIdx.x;
    const int warp = tid >> 5;
    const int lane = tid & 31;
    const int g = lane >> 2, tig = lane & 3;
    const int wm = (warp >> 1) * 32;
    const int wn = (warp & 1) * 64;

    #pragma unroll
    for (int mt = 0; mt < 2; mt++)
        #pragma unroll
        for (int nt = 0; nt < 8; nt++)
            #pragma unroll
            for (int r = 0; r < 4; r++) R.acc[mt][nt][r] = 0.f;

    gemm_issue(S, 0, Ag, Bg, m0, n0, 0, tid);

    #pragma unroll 1
    for (int kt = 0; kt < CDIM / GBK; kt++) {
        if (kt < CDIM / GBK - 1) {
            gemm_issue(S, (kt + 1) & 1, Ag, Bg, m0, n0, (kt + 1) * GBK, tid);
            cp_wait1();
        } else {
            cp_wait0();
        }
        __syncthreads();

        const uint32_t* As = S->As[kt & 1];
        const uint32_t* Bs = S->Bs[kt & 1];

        #pragma unroll
        for (int ks = 0; ks < 2; ks++) {
            int kk = ks * 8;
            uint32_t af[2][4];
            #pragma unroll
            for (int mt = 0; mt < 2; mt++) {
                int r = wm + 16 * mt;
                af[mt][0] = As[(r + g) * APAD + kk + tig];
                af[mt][1] = As[(r + g + 8) * APAD + kk + tig];
                af[mt][2] = As[(r + g) * APAD + kk + tig + 4];
                af[mt][3] = As[(r + g + 8) * APAD + kk + tig + 4];
            }
            #pragma unroll
            for (int nt = 0; nt < 8; nt++) {
                uint32_t b0 = Bs[(kk + tig) * BPAD + wn + 8 * nt + g];
                uint32_t b1 = Bs[(kk + tig + 4) * BPAD + wn + 8 * nt + g];
                mma_tf32(R.acc[0][nt], af[0][0], af[0][1], af[0][2], af[0][3], b0, b1);
                mma_tf32(R.acc[1][nt], af[1][0], af[1][1], af[1][2], af[1][3], b0, b1);
            }
        }
        __syncthreads();
    }
}

// Kernel 1: QKV projection -> head-major scratch (pre-rounded to tf32).
__global__ __launch_bounds__(256) void qkv_gemm_kernel()
{
    __shared__ GemmSmem S;
    const int b = blockIdx.z;
    const int m0 = blockIdx.y * GBM;
    const int n0 = blockIdx.x * GBN;

    GemmAcc R;
    gemm_core(&S, g_wq, g_xt + (size_t)b * CDIM * NN, m0, n0, R);

    const int tid = threadIdx.x;
    const int warp = tid >> 5, lane = tid & 31;
    const int g = lane >> 2, tig = lane & 3;
    const int wm = (warp >> 1) * 32, wn = (warp & 1) * 64;

    #pragma unroll
    for (int mt = 0; mt < 2; mt++) {
        #pragma unroll
        for (int half = 0; half < 2; half++) {
            int o = m0 + wm + 16 * mt + g + 8 * half;
            int grp = o >> 8;
            int hh = (o >> 5) & 7;
            int dd = o & 31;
            float* dst = (grp == 0) ? g_qt : (grp == 1) ? g_kt : g_vt;
            float sc = (grp == 0) ? SCALE_F : 1.0f;
            size_t base = ((size_t)(b * NH + hh) * NN) * ND + dd;
            #pragma unroll
            for (int nt = 0; nt < 8; nt++) {
                int n = n0 + wn + 8 * nt + 2 * tig;
                dst[base + (size_t)n * ND]       = f2tff(R.acc[mt][nt][2 * half] * sc);
                dst[base + (size_t)(n + 1) * ND] = f2tff(R.acc[mt][nt][2 * half + 1] * sc);
            }
        }
    }
}

// Kernel 3: output projection + bias.
__global__ __launch_bounds__(256) void out_gemm_kernel(const float* __restrict__ bias,
                                                       float* __restrict__ Y)
{
    __shared__ GemmSmem S;
    const int b = blockIdx.z;
    const int m0 = blockIdx.y * GBM;
    const int n0 = blockIdx.x * GBN;

    GemmAcc R;
    gemm_core(&S, g_wo, g_ao + (size_t)b * CDIM * NN, m0, n0, R);

    const int tid = threadIdx.x;
    const int warp = tid >> 5, lane = tid & 31;
    const int g = lane >> 2, tig = lane & 3;
    const int wm = (warp >> 1) * 32, wn = (warp & 1) * 64;

    #pragma unroll
    for (int mt = 0; mt < 2; mt++) {
        #pragma unroll
        for (int half = 0; half < 2; half++) {
            int o = m0 + wm + 16 * mt + g + 8 * half;
            float bv = bias[o];
            float* yrow = Y + ((size_t)b * CDIM + o) * NN;
            #pragma unroll
            for (int nt = 0; nt < 8; nt++) {
                int n = n0 + wn + 8 * nt + 2 * tig;
                yrow[n]     = R.acc[mt][nt][2 * half]     + bv;
                yrow[n + 1] = R.acc[mt][nt][2 * half + 1] + bv;
            }
        }
    }
}

// ---------------------------------------------------------------------------
// Kernel 2: flash attention, tf32 MMA, cp.async double-buffered K/V tiles.
// CTA = 128 threads (4 warps), Br=64 (16/warp), Bc=32, d=32. STATIC smem 37KB.
// ---------------------------------------------------------------------------
#define QPAD 36
#define KPAD 36
#define VPAD 40
#define PPAD 36
#define BC   32

struct AttnSmem {
    uint32_t Qs[64 * QPAD];
    uint32_t Ks[2][BC * KPAD];
    uint32_t Vs[2][BC * VPAD];
    uint32_t Ps[4][16 * PPAD];
};

__device__ __forceinline__ void attn_issue(AttnSmem* S, int s,
                                           const float* __restrict__ Kg,
                                           const float* __restrict__ Vg,
                                           int j0, int tid)
{
    uint32_t k_base = (uint32_t)__cvta_generic_to_shared(&S->Ks[s][0]);
    uint32_t v_base = (uint32_t)__cvta_generic_to_shared(&S->Vs[s][0]);
    // K,V tiles 32x32 = 256 f4 each; 128 threads -> 2 each
    #pragma unroll
    for (int i = 0; i < 2; i++) {
        int slot = i * 128 + tid;
        int row = slot >> 3, f4 = slot & 7;
        cp16(k_base + (uint32_t)(row * KPAD + 4 * f4) * 4,
             Kg + (size_t)(j0 + row) * ND + 4 * f4);
        cp16(v_base + (uint32_t)(row * VPAD + 4 * f4) * 4,
             Vg + (size_t)(j0 + row) * ND + 4 * f4);
    }
    cp_commit();
}

__global__ __launch_bounds__(128) void attn_kernel()
{
    __shared__ AttnSmem S;

    const int b = blockIdx.z;
    const int h = blockIdx.y;
    const int q0 = blockIdx.x * 64;

    const int tid = threadIdx.x;
    const int warp = tid >> 5, lane = tid & 31;
    const int g = lane >> 2, tig = lane & 3;

    const size_t headBase = (size_t)(b * NH + h) * NN * ND;
    const float* Qg = g_qt + headBase;
    const float* Kg = g_kt + headBase;
    const float* Vg = g_vt + headBase;

    // Prefetch tile 0
    attn_issue(&S, 0, Kg, Vg, 0, tid);

    // Load Q tile (64x32), already tf32-rounded
    #pragma unroll
    for (int i = 0; i < 4; i++) {
        int slot = i * 128 + tid;
        int row = slot >> 3, f4 = slot & 7;
        float4 qv = *(const float4*)&Qg[(size_t)(q0 + row) * ND + 4 * f4];
        uint4 u;
        u.x = __float_as_uint(qv.x); u.y = __float_as_uint(qv.y);
        u.z = __float_as_uint(qv.z); u.w = __float_as_uint(qv.w);
        *(uint4*)&S.Qs[row * QPAD + 4 * f4] = u;
    }
    __syncthreads();

    // Hoist Q frags (warp owns rows [16*warp, 16*warp+16))
    uint32_t qf[4][4];
    #pragma unroll
    for (int ks = 0; ks < 4; ks++) {
        int kk = 8 * ks;
        int r = 16 * warp;
        qf[ks][0] = S.Qs[(r + g) * QPAD + kk + tig];
        qf[ks][1] = S.Qs[(r + g + 8) * QPAD + kk + tig];
        qf[ks][2] = S.Qs[(r + g) * QPAD + kk + tig + 4];
        qf[ks][3] = S.Qs[(r + g + 8) * QPAD + kk + tig + 4];
    }

    float oacc[4][4];
    #pragma unroll
    for (int dt = 0; dt < 4; dt++)
        #pragma unroll
        for (int r = 0; r < 4; r++) oacc[dt][r] = 0.f;
    float m0 = -1e30f, m1 = -1e30f, l0 = 0.f, l1 = 0.f;

    uint32_t* Pw = S.Ps[warp];

    #pragma unroll 1
    for (int t = 0; t < NN / BC; t++) {
        if (t < NN / BC - 1) {
            attn_issue(&S, (t + 1) & 1, Kg, Vg, (t + 1) * BC, tid);
            cp_wait1();
        } else {
            cp_wait0();
        }
        __syncthreads();

        const uint32_t* Ks = S.Ks[t & 1];
        const uint32_t* Vs = S.Vs[t & 1];

        // S = Q K^T : [16 x 32] per warp
        float sacc[4][4];
        #pragma unroll
        for (int nt = 0; nt < 4; nt++)
            #pragma unroll
            for (int r = 0; r < 4; r++) sacc[nt][r] = 0.f;
        #pragma unroll
        for (int ks = 0; ks < 4; ks++) {
            int kk = 8 * ks;
            #pragma unroll
            for (int nt = 0; nt < 4; nt++) {
                uint32_t b0 = Ks[(8 * nt + g) * KPAD + kk + tig];
                uint32_t b1 = Ks[(8 * nt + g) * KPAD + kk + tig + 4];
                mma_tf32(sacc[nt], qf[ks][0], qf[ks][1], qf[ks][2], qf[ks][3], b0, b1);
            }
        }

        // Online softmax
        float mx0 = -1e30f, mx1 = -1e30f;
        #pragma unroll
        for (int nt = 0; nt < 4; nt++) {
            mx0 = fmaxf(mx0, fmaxf(sacc[nt][0], sacc[nt][1]));
            mx1 = fmaxf(mx1, fmaxf(sacc[nt][2], sacc[nt][3]));
        }
        mx0 = fmaxf(mx0, __shfl_xor_sync(0xffffffff, mx0, 1));
        mx0 = fmaxf(mx0, __shfl_xor_sync(0xffffffff, mx0, 2));
        mx1 = fmaxf(mx1, __shfl_xor_sync(0xffffffff, mx1, 1));
        mx1 = fmaxf(mx1, __shfl_xor_sync(0xffffffff, mx1, 2));

        float mn0 = fmaxf(m0, mx0);
        float mn1 = fmaxf(m1, mx1);
        float sc0 = ex2f((m0 - mn0) * L2E);
        float sc1 = ex2f((m1 - mn1) * L2E);
        m0 = mn0; m1 = mn1;
        float mb0 = mn0 * L2E, mb1 = mn1 * L2E;

        float sum0 = 0.f, sum1 = 0.f;
        float p[4][4];
        #pragma unroll
        for (int nt = 0; nt < 4; nt++) {
            p[nt][0] = ex2f(fmaf(sacc[nt][0], L2E, -mb0));
            p[nt][1] = ex2f(fmaf(sacc[nt][1], L2E, -mb0));
            p[nt][2] = ex2f(fmaf(sacc[nt][2], L2E, -mb1));
            p[nt][3] = ex2f(fmaf(sacc[nt][3], L2E, -mb1));
            sum0 += p[nt][0] + p[nt][1];
            sum1 += p[nt][2] + p[nt][3];
        }
        sum0 += __shfl_xor_sync(0xffffffff, sum0, 1);
        sum0 += __shfl_xor_sync(0xffffffff, sum0, 2);
        sum1 += __shfl_xor_sync(0xffffffff, sum1, 1);
        sum1 += __shfl_xor_sync(0xffffffff, sum1, 2);
        l0 = l0 * sc0 + sum0;
        l1 = l1 * sc1 + sum1;

        #pragma unroll
        for (int dt = 0; dt < 4; dt++) {
            oacc[dt][0] *= sc0; oacc[dt][1] *= sc0;
            oacc[dt][2] *= sc1; oacc[dt][3] *= sc1;
        }

        // Store P (tf32) to warp-private smem
        #pragma unroll
        for (int nt = 0; nt < 4; nt++) {
            uint2 u0, u1;
            u0.x = f2tf(p[nt][0]); u0.y = f2tf(p[nt][1]);
            u1.x = f2tf(p[nt][2]); u1.y = f2tf(p[nt][3]);
            *(uint2*)&Pw[g * PPAD + 8 * nt + 2 * tig]       = u0;
            *(uint2*)&Pw[(g + 8) * PPAD + 8 * nt + 2 * tig] = u1;
        }
        __syncwarp();

        // O += P V : A = P [16x32], B = V [32x32]
        #pragma unroll
        for (int ks2 = 0; ks2 < 4; ks2++) {
            int kk = 8 * ks2;
            uint32_t a0 = Pw[g * PPAD + kk + tig];
            uint32_t a1 = Pw[(g + 8) * PPAD + kk + tig];
            uint32_t a2 = Pw[g * PPAD + kk + tig + 4];
            uint32_t a3 = Pw[(g + 8) * PPAD + kk + tig + 4];
            #pragma unroll
            for (int dt = 0; dt < 4; dt++) {
                uint32_t b0 = Vs[(kk + tig) * VPAD + 8 * dt + g];
                uint32_t b1 = Vs[(kk + tig + 4) * VPAD + 8 * dt + g];
                mma_tf32(oacc[dt], a0, a1, a2, a3, b0, b1);
            }
        }
        __syncwarp();
        __syncthreads();
    }

    // Epilogue: normalize, round, write [b][c][n]
    float inv0 = 1.0f / l0;
    float inv1 = 1.0f / l1;
    int n_row0 = q0 + 16 * warp + g;
    float* aoB = g_ao + ((size_t)b * CDIM + h * ND) * NN;
    #pragma unroll
    for (int dt = 0; dt < 4; dt++) {
        int d = 8 * dt + 2 * tig;
        aoB[(size_t)d * NN + n_row0]           = f2tff(oacc[dt][0] * inv0);
        aoB[(size_t)(d + 1) * NN + n_row0]     = f2tff(oacc[dt][1] * inv0);
        aoB[(size_t)d * NN + n_row0 + 8]       = f2tff(oacc[dt][2] * inv1);
        aoB[(size_t)(d + 1) * NN + n_row0 + 8] = f2tff(oacc[dt][3] * inv1);
    }
}

// ---------------------------------------------------------------------------
extern "C" void kernel_launch(void* const* d_in, const int* in_sizes, int n_in,
                              void* d_out, int out_size)
{
    const float* x     = (const float*)d_in[0];
    const float* w_qkv = (const float*)d_in[1];
    const float* w_out = (const float*)d_in[2];
    const float* b_out = (const float*)d_in[3];
    float* y = (float*)d_out;

    int cvtBlocks = (NX4 + NWQ4 + NWO4 + 255) / 256;
    cvt_kernel<<<cvtBlocks, 256>>>(x, w_qkv, w_out);
    qkv_gemm_kernel<<<dim3(NN / GBN, QKV_M / GBM, NB), 256>>>();
    attn_kernel<<<dim3(NN / 64, NH, NB), 128>>>();
    out_gemm_kernel<<<dim3(NN / GBN, CDIM / GBM, NB), 256>>>(b_out, y);
}